// round 16
// baseline (speedup 1.0000x reference)
#include <cuda_runtime.h>
#include <cuda_bf16.h>
#include <cuda_fp16.h>
#include <cstdint>
#include <math.h>

#define CH 192
#define DD 24
#define BB 8
#define LL 4096
#define NTOK (BB*LL)
#define BQ 128
#define BK 256
#define NKT (LL/BK)

#define APAD 26
#define QPH 16                        // u32 per Q row (12 data + 4 zero)
#define KROWW 132                     // u32 per K ch-row (128 + 4 pad)
#define VROWW 20                      // u32 per V key-row (12 data + 4 static + 4 pad)
#define LOG2E 1.4426950408889634f

// ---- proj smem layout (floats) ----
#define XP 52
#define POFF_W 6656
#define P_FLOATS (POFF_W + 72*XP)

// ---- attn smem layout (u32 words) ----
#define OFF_Q 0                       // 128*16        = 2048
#define OFF_K 2048                    // 32*132        = 4224   (ch rows 24..31 zero)
#define OFF_V 6272                    // 256*20        = 5120
#define SM_U32 11392                  // 45568 B
#define WOFF 4096                     // Wo floats at [4096, 4096+1152)

__device__ uint32_t g_qh[NTOK*12];          // packed half2 q channel-pairs, log2e folded
__device__ uint32_t g_kt[BB*24*(LL/2)];     // [b][ch][key/2] half2 {k[2p][ch], k[2p+1][ch]}
__device__ uint32_t g_vt[(size_t)NTOK*12];  // [tok][12] bf16x2 d-pairs (packed, no constants)

// ---------------------------------------------------------------------------
// helpers
// ---------------------------------------------------------------------------
__device__ __forceinline__ void mma_tf32(float* c, const uint32_t* a, uint32_t b0, uint32_t b1){
    asm volatile("mma.sync.aligned.m16n8k8.row.col.f32.tf32.tf32.f32 "
        "{%0,%1,%2,%3}, {%4,%5,%6,%7}, {%8,%9}, {%0,%1,%2,%3};"
        : "+f"(c[0]), "+f"(c[1]), "+f"(c[2]), "+f"(c[3])
        : "r"(a[0]), "r"(a[1]), "r"(a[2]), "r"(a[3]), "r"(b0), "r"(b1));
}
__device__ __forceinline__ void mma_f16(float* c, const uint32_t* a, uint32_t b0, uint32_t b1){
    asm volatile("mma.sync.aligned.m16n8k16.row.col.f32.f16.f16.f32 "
        "{%0,%1,%2,%3}, {%4,%5,%6,%7}, {%8,%9}, {%0,%1,%2,%3};"
        : "+f"(c[0]), "+f"(c[1]), "+f"(c[2]), "+f"(c[3])
        : "r"(a[0]), "r"(a[1]), "r"(a[2]), "r"(a[3]), "r"(b0), "r"(b1));
}
__device__ __forceinline__ void mma_bf16(float* c, const uint32_t* a, uint32_t b0, uint32_t b1){
    asm volatile("mma.sync.aligned.m16n8k16.row.col.f32.bf16.bf16.f32 "
        "{%0,%1,%2,%3}, {%4,%5,%6,%7}, {%8,%9}, {%0,%1,%2,%3};"
        : "+f"(c[0]), "+f"(c[1]), "+f"(c[2]), "+f"(c[3])
        : "r"(a[0]), "r"(a[1]), "r"(a[2]), "r"(a[3]), "r"(b0), "r"(b1));
}
__device__ __forceinline__ void ldmx4t(uint32_t& a, uint32_t& b, uint32_t& c, uint32_t& d, uint32_t addr){
    asm volatile("ldmatrix.sync.aligned.m8n8.x4.trans.shared.b16 {%0,%1,%2,%3}, [%4];"
        : "=r"(a), "=r"(b), "=r"(c), "=r"(d) : "r"(addr));
}
__device__ __forceinline__ uint32_t packbf(float hi, float lo){
    uint32_t r;
    asm("cvt.rn.bf16x2.f32 %0, %1, %2;" : "=r"(r) : "f"(hi), "f"(lo));
    return r;
}
__device__ __forceinline__ uint32_t packh2(float hi, float lo){
    uint32_t r;
    asm("cvt.rn.f16x2.f32 %0, %1, %2;" : "=r"(r) : "f"(hi), "f"(lo));
    return r;
}
__device__ __forceinline__ float ex2f(float x){
    float y;
    asm("ex2.approx.f32 %0, %1;" : "=f"(y) : "f"(x));
    return y;
}
__device__ __forceinline__ uint32_t smem_u32(const void* p){
    uint32_t a;
    asm("{ .reg .u64 t; cvta.to.shared.u64 t, %1; cvt.u32.u64 %0, t; }":"=r"(a):"l"(p));
    return a;
}
__device__ __forceinline__ void cp16(uint32_t dst, const void* src){
    asm volatile("cp.async.ca.shared.global [%0], [%1], 16;"::"r"(dst),"l"(src):"memory");
}
#define CP_COMMIT() asm volatile("cp.async.commit_group;":::"memory")
#define CP_WAIT0()  asm volatile("cp.async.wait_group 0;":::"memory")

// ---------------------------------------------------------------------------
// Kernel 1: tf32 MMA QKV projection. Coalesced W staging (R15). Outputs:
// q packed fp16 (log2e folded); K [ch][key-pair] fp16; V [tok][12] bf16 pairs.
// ---------------------------------------------------------------------------
__global__ __launch_bounds__(128) void proj_mma_kernel(
    const float* __restrict__ x, const float* __restrict__ wq,
    const float* __restrict__ wk, const float* __restrict__ wv)
{
    extern __shared__ float sm[];
    float* Xs  = sm;
    float* Wts = sm + POFF_W;

    const int tid  = threadIdx.x;
    const int w    = tid >> 5;
    const int lane = tid & 31;
    const int g    = lane >> 2;
    const int tig  = lane & 3;
    const int tok0 = blockIdx.x * 128;

    float c[2][9][4];
    #pragma unroll
    for (int mt = 0; mt < 2; mt++)
        #pragma unroll
        for (int nt = 0; nt < 9; nt++)
            #pragma unroll
            for (int j = 0; j < 4; j++) c[mt][nt][j] = 0.f;

    #pragma unroll 1
    for (int ch = 0; ch < 4; ch++) {
        __syncthreads();
        // stage X chunk: row tid, 48 channels = 12 float4 (coalesced)
        {
            const float4* xsrc = reinterpret_cast<const float4*>(x + (size_t)(tok0 + tid)*CH + ch*48);
            float4* xdst = reinterpret_cast<float4*>(Xs + tid*XP);
            #pragma unroll
            for (int i = 0; i < 12; i++) xdst[i] = xsrc[i];
        }
        // stage Wt chunk COALESCED: rows are 24 floats = 6 float4; scatter-
        // transpose into Wts[o][cl]. 288 float4 triples per chunk.
        for (int i = tid; i < 288; i += 128) {
            int cl = i / 6, f4 = i - cl*6;
            int cg = ch*48 + cl;
            float4 aq = *reinterpret_cast<const float4*>(wq + cg*DD + f4*4);
            float4 ak = *reinterpret_cast<const float4*>(wk + cg*DD + f4*4);
            float4 av = *reinterpret_cast<const float4*>(wv + cg*DD + f4*4);
            float* col = Wts + cl;
            col[(f4*4+0)*XP] = aq.x*LOG2E;
            col[(f4*4+1)*XP] = aq.y*LOG2E;
            col[(f4*4+2)*XP] = aq.z*LOG2E;
            col[(f4*4+3)*XP] = aq.w*LOG2E;
            col[(24+f4*4+0)*XP] = ak.x;
            col[(24+f4*4+1)*XP] = ak.y;
            col[(24+f4*4+2)*XP] = ak.z;
            col[(24+f4*4+3)*XP] = ak.w;
            col[(48+f4*4+0)*XP] = av.x;
            col[(48+f4*4+1)*XP] = av.y;
            col[(48+f4*4+2)*XP] = av.z;
            col[(48+f4*4+3)*XP] = av.w;
        }
        __syncthreads();

        #pragma unroll
        for (int ks = 0; ks < 6; ks++) {
            uint32_t a[2][4];
            #pragma unroll
            for (int mt = 0; mt < 2; mt++) {
                const float* r0 = Xs + (w*32 + mt*16 + g)*XP + ks*8 + tig;
                const float* r1 = r0 + 8*XP;
                a[mt][0] = __float_as_uint(r0[0]);
                a[mt][1] = __float_as_uint(r1[0]);
                a[mt][2] = __float_as_uint(r0[4]);
                a[mt][3] = __float_as_uint(r1[4]);
            }
            #pragma unroll
            for (int nt = 0; nt < 9; nt++) {
                const float* br = Wts + (nt*8 + g)*XP + ks*8 + tig;
                uint32_t b0 = __float_as_uint(br[0]);
                uint32_t b1 = __float_as_uint(br[4]);
                mma_tf32(c[0][nt], a[0], b0, b1);
                mma_tf32(c[1][nt], a[1], b0, b1);
            }
        }
    }

    // ---- bounce C to smem [128][76] ----
    __syncthreads();
    #pragma unroll
    for (int mt = 0; mt < 2; mt++)
        #pragma unroll
        for (int h = 0; h < 2; h++) {
            int row = w*32 + mt*16 + g + h*8;
            #pragma unroll
            for (int nt = 0; nt < 9; nt++) {
                sm[row*76 + nt*8 + 2*tig]     = c[mt][nt][h*2];
                sm[row*76 + nt*8 + 2*tig + 1] = c[mt][nt][h*2+1];
            }
        }
    __syncthreads();

    // ---- q packed fp16 pairs ----
    {
        int tok = tok0 + tid;
        const float* r = sm + tid*76;
        uint32_t qw[12];
        #pragma unroll
        for (int cp = 0; cp < 12; cp++) qw[cp] = packh2(r[2*cp+1], r[2*cp]);
        uint4* qo = reinterpret_cast<uint4*>(g_qh + (size_t)tok*12);
        qo[0] = make_uint4(qw[0], qw[1], qw[2],  qw[3]);
        qo[1] = make_uint4(qw[4], qw[5], qw[6],  qw[7]);
        qo[2] = make_uint4(qw[8], qw[9], qw[10], qw[11]);
    }
    // ---- K: g_kt[b][ch][p] = {k[2p][ch], k[2p+1][ch]} fp16 ----
    {
        int b0i  = tok0 / LL;
        int koff = (tok0 - b0i*LL) / 2;
        uint32_t* dst = g_kt + (size_t)b0i*24*(LL/2) + koff;
        #pragma unroll
        for (int i = 0; i < 12; i++) {
            int idx = tid + i*128;       // < 1536
            int ch = idx >> 6, p = idx & 63;
            dst[(size_t)ch*(LL/2) + p] =
                packh2(sm[(2*p+1)*76 + 24 + ch], sm[(2*p)*76 + 24 + ch]);
        }
    }
    // ---- V: g_vt[tok][12] bf16 d-pairs (packed, no constants) ----
    {
        int tok = tok0 + tid;
        const float* r = sm + tid*76 + 48;
        uint32_t vw[12];
        #pragma unroll
        for (int j = 0; j < 12; j++) vw[j] = packbf(r[2*j+1], r[2*j]);
        uint4* vo = reinterpret_cast<uint4*>(g_vt + (size_t)tok*12);
        vo[0] = make_uint4(vw[0], vw[1], vw[2],  vw[3]);
        vo[1] = make_uint4(vw[4], vw[5], vw[6],  vw[7]);
        vo[2] = make_uint4(vw[8], vw[9], vw[10], vw[11]);
    }
}

// ---------------------------------------------------------------------------
// Kernel 2: mma.sync flash attention (BQ=128, 4 warps x 32 q). fp16 QK^T +
// bf16 PV via ldmatrix, max-free softmax. V staged packed (3 cp16/key);
// ones-column words initialized once.
// ---------------------------------------------------------------------------
__global__ __launch_bounds__(128, 3) void attn_mma_kernel(
    const float* __restrict__ tensor, const float* __restrict__ wo,
    const float* __restrict__ gammap, float* __restrict__ out)
{
    extern __shared__ float smf[];
    uint32_t* Qh = reinterpret_cast<uint32_t*>(smf) + OFF_Q;
    uint32_t* Kw = reinterpret_cast<uint32_t*>(smf) + OFF_K;
    uint32_t* Vw = reinterpret_cast<uint32_t*>(smf) + OFF_V;
    const uint32_t smb = smem_u32(smf);

    const int tid  = threadIdx.x;
    const int w    = tid >> 5;
    const int lane = tid & 31;
    const int g    = lane >> 2;
    const int tig  = lane & 3;
    const int qt = blockIdx.x, b = blockIdx.y;

    // per-lane ldmatrix row-offset bases (halves)
    const int t8  = lane >> 3;
    const int tg8 = lane & 7;
    const uint32_t kaddr0 = smb + OFF_K*4 + (((t8 & 1)*8 + tg8)*(KROWW*2) + (t8 >> 1)*8)*2;
    const uint32_t vaddr0 = smb + OFF_V*4 + (((t8 & 1)*8 + tg8)*(VROWW*2) + (t8 >> 1)*8)*2;

    // ---- stage Q tile: 12 packed words + 4 zero words per row ----
    {
        int tok = b*LL + qt*BQ + tid;
        const uint4* src = reinterpret_cast<const uint4*>(g_qh + (size_t)tok*12);
        uint4* dst = reinterpret_cast<uint4*>(Qh + tid*QPH);
        dst[0] = src[0]; dst[1] = src[1]; dst[2] = src[2];
        dst[3] = make_uint4(0u, 0u, 0u, 0u);
    }
    // ---- static pads (once): K ch-rows 24..31 zero; V words 12..15 per key ----
    for (int i = tid; i < 8*KROWW; i += 128) Kw[24*KROWW + i] = 0;
    #pragma unroll
    for (int r = 0; r < 2; r++) {
        int key = tid + r*128;
        Vw[key*VROWW + 12] = 0x00003F80u;   // d24 = bf16 1.0 (l column), d25 = 0
        Vw[key*VROWW + 13] = 0u;
        Vw[key*VROWW + 14] = 0u;
        Vw[key*VROWW + 15] = 0u;
    }
    __syncthreads();

    // ---- Q fragments: warp owns 32 rows (2 m-tiles), 2 k-steps of 16 ----
    uint32_t qa[2][2][4];
    #pragma unroll
    for (int mt = 0; mt < 2; mt++)
        #pragma unroll
        for (int ks = 0; ks < 2; ks++) {
            const uint32_t* r0 = Qh + (w*32 + mt*16 + g)*QPH + ks*8 + tig;
            const uint32_t* r1 = r0 + 8*QPH;
            qa[mt][ks][0] = r0[0];
            qa[mt][ks][1] = r1[0];
            qa[mt][ks][2] = r0[4];
            qa[mt][ks][3] = r1[4];
        }

    // O accumulators: 4 n-tiles (3 V dims + ones-column carrying l)
    float o[2][4][4];
    #pragma unroll
    for (int mt = 0; mt < 2; mt++)
        #pragma unroll
        for (int dn = 0; dn < 4; dn++)
            #pragma unroll
            for (int j = 0; j < 4; j++) o[mt][dn][j] = 0.f;

    // ================= main loop =================
    #pragma unroll 1
    for (int kt = 0; kt < NKT; kt++) {
        __syncthreads();
        {
            // K: 24 ch-rows x 32 word-groups = 768 cp16
            const uint32_t* ksrc = g_kt + (size_t)b*24*(LL/2) + kt*(BK/2);
            #pragma unroll
            for (int i = 0; i < 6; i++) {
                int idx = tid + i*128;           // < 768
                int ch = idx >> 5, grp = idx & 31;
                cp16(smb + (OFF_K + ch*KROWW + grp*4)*4, ksrc + (size_t)ch*(LL/2) + grp*4);
            }
            // V: flat contiguous 768 cp16 (256 keys x 3 groups); dst scatter
            const uint32_t* vsrc = g_vt + ((size_t)b*LL + kt*BK)*12;
            #pragma unroll
            for (int i = 0; i < 6; i++) {
                int idx = tid + i*128;           // < 768
                int key = idx / 3;               // dst word = idx*4 + key*8
                cp16(smb + (OFF_V + idx*4 + key*8)*4, vsrc + (size_t)idx*4);
            }
            CP_COMMIT();
            CP_WAIT0();
        }
        __syncthreads();

        // ---- 4 chunks of 64 keys ----
        #pragma unroll 1
        for (int ck = 0; ck < 4; ck++) {
            float s[2][8][4];
            #pragma unroll
            for (int mt = 0; mt < 2; mt++)
                #pragma unroll
                for (int nt = 0; nt < 8; nt++)
                    #pragma unroll
                    for (int j = 0; j < 4; j++) s[mt][nt][j] = 0.f;

            // S = Q K^T (fp16, m16n8k16), log2 units; K frags via ldmatrix
            #pragma unroll
            for (int ks = 0; ks < 2; ks++)
                #pragma unroll
                for (int ntp = 0; ntp < 4; ntp++) {
                    uint32_t b0, b1, b2, b3;
                    ldmx4t(b0, b1, b2, b3,
                           kaddr0 + (uint32_t)(ks*16*(KROWW*2) + ck*64 + ntp*16)*2);
                    mma_f16(s[0][2*ntp],   qa[0][ks], b0, b1);
                    mma_f16(s[1][2*ntp],   qa[1][ks], b0, b1);
                    mma_f16(s[0][2*ntp+1], qa[0][ks], b2, b3);
                    mma_f16(s[1][2*ntp+1], qa[1][ks], b2, b3);
                }

            // p = 2^s  (no max, no rescale)
            #pragma unroll
            for (int mt = 0; mt < 2; mt++)
                #pragma unroll
                for (int nt = 0; nt < 8; nt++)
                    #pragma unroll
                    for (int j = 0; j < 4; j++)
                        s[mt][nt][j] = ex2f(s[mt][nt][j]);

            // O += P V (bf16); V frags via ldmatrix; n-tile 3 carries l
            #pragma unroll
            for (int ks2 = 0; ks2 < 4; ks2++) {
                uint32_t pa[2][4];
                #pragma unroll
                for (int mt = 0; mt < 2; mt++) {
                    pa[mt][0] = packbf(s[mt][ks2*2][1],   s[mt][ks2*2][0]);
                    pa[mt][1] = packbf(s[mt][ks2*2][3],   s[mt][ks2*2][2]);
                    pa[mt][2] = packbf(s[mt][ks2*2+1][1], s[mt][ks2*2+1][0]);
                    pa[mt][3] = packbf(s[mt][ks2*2+1][3], s[mt][ks2*2+1][2]);
                }
                #pragma unroll
                for (int dnp = 0; dnp < 2; dnp++) {
                    uint32_t b0, b1, b2, b3;
                    ldmx4t(b0, b1, b2, b3,
                           vaddr0 + (uint32_t)((ck*64 + ks2*16)*(VROWW*2) + dnp*16)*2);
                    mma_bf16(o[0][2*dnp],   pa[0], b0, b1);
                    mma_bf16(o[1][2*dnp],   pa[1], b0, b1);
                    mma_bf16(o[0][2*dnp+1], pa[0], b2, b3);
                    mma_bf16(o[1][2*dnp+1], pa[1], b2, b3);
                }
            }
        }
    }

    // ---- write normalized attn (transpose bounce at 0), stage Wo at WOFF ----
    __syncthreads();
    {
        #pragma unroll
        for (int mt = 0; mt < 2; mt++)
            #pragma unroll
            for (int h = 0; h < 2; h++) {
                float lv = __shfl_sync(0xffffffffu, o[mt][3][h*2], lane & 28);
                float inv = 1.0f / lv;
                int row = w*32 + mt*16 + g + h*8;
                #pragma unroll
                for (int dn = 0; dn < 3; dn++) {
                    smf[row*APAD + dn*8 + 2*tig]     = o[mt][dn][h*2]   * inv;
                    smf[row*APAD + dn*8 + 2*tig + 1] = o[mt][dn][h*2+1] * inv;
                }
            }
        float4* wd = reinterpret_cast<float4*>(smf + WOFF);
        const float4* ws = reinterpret_cast<const float4*>(wo);
        #pragma unroll
        for (int i = 0; i < 9; i++) wd[tid + i*128] = ws[tid + i*128];
    }
    __syncthreads();

    // ---- epilogue: out = tensor + gamma * attn @ Wo ----
    float attn[DD];
    #pragma unroll
    for (int d = 0; d < DD; d++) attn[d] = smf[tid*APAD + d];

    float gm = *gammap;
    int tok = b*LL + qt*BQ + tid;
    const float4* tr = reinterpret_cast<const float4*>(tensor + (size_t)tok * CH);
    float4* orow = reinterpret_cast<float4*>(out + (size_t)tok * CH);
    const float4* wos = reinterpret_cast<const float4*>(smf + WOFF);

    #pragma unroll 1
    for (int c4 = 0; c4 < CH/4; c4++) {
        float4 t = tr[c4];
        float sx = 0.f, sy = 0.f, sz = 0.f, sw = 0.f;
        #pragma unroll
        for (int d = 0; d < DD; d++) {
            float4 wv4 = wos[d*48 + c4];
            sx = fmaf(attn[d], wv4.x, sx);
            sy = fmaf(attn[d], wv4.y, sy);
            sz = fmaf(attn[d], wv4.z, sz);
            sw = fmaf(attn[d], wv4.w, sw);
        }
        t.x = fmaf(gm, sx, t.x);
        t.y = fmaf(gm, sy, t.y);
        t.z = fmaf(gm, sz, t.z);
        t.w = fmaf(gm, sw, t.w);
        orow[c4] = t;
    }
}

extern "C" void kernel_launch(void* const* d_in, const int* in_sizes, int n_in,
                              void* d_out, int out_size)
{
    const float* tensor = (const float*)d_in[0];
    const float* wq     = (const float*)d_in[1];
    const float* wk     = (const float*)d_in[2];
    const float* wv     = (const float*)d_in[3];
    const float* wo     = (const float*)d_in[4];
    const float* gamma  = (const float*)d_in[5];
    float* out = (float*)d_out;

    cudaFuncSetAttribute(attn_mma_kernel, cudaFuncAttributeMaxDynamicSharedMemorySize, SM_U32*4);

    proj_mma_kernel<<<NTOK/128, 128, P_FLOATS*4>>>(tensor, wq, wk, wv);

    dim3 g2(LL/BQ, BB);
    attn_mma_kernel<<<g2, 128, SM_U32*4>>>(tensor, wo, gamma, out);
}

// round 17
// speedup vs baseline: 1.0180x; 1.0180x over previous
#include <cuda_runtime.h>
#include <cuda_bf16.h>
#include <cuda_fp16.h>
#include <cstdint>
#include <math.h>

#define CH 192
#define DD 24
#define BB 8
#define LL 4096
#define NTOK (BB*LL)
#define BQ 128
#define BK 256
#define NKT (LL/BK)

#define APAD 26
#define QPH 16                        // u32 per Q row (12 data + 4 zero)
#define KROWW 132                     // u32 per K ch-row (128 + 4 pad)
#define VROWW 20                      // u32 per V key-row (12 data + 4 static + 4 pad)
#define LOG2E 1.4426950408889634f

// ---- proj smem layout (floats) ----
#define XP 52
#define POFF_W 6656
#define P_FLOATS (POFF_W + 72*XP)

// ---- attn smem layout (u32 words) ----
#define OFF_Q 0                       // 128*16        = 2048
#define OFF_K 2048                    // 32*132        = 4224   (ch rows 24..31 zero)
#define OFF_V 6272                    // 256*20        = 5120
#define SM_U32 11392                  // 45568 B
// epilogue float layout (reuses whole smem): bounce0 [0,3328), bounce1 [3328,6656), Wo [6656,7808)
#define BNC1 3328
#define WOFF 6656

__device__ uint32_t g_qh[NTOK*12];          // packed half2 q channel-pairs, log2e folded
__device__ uint32_t g_kt[BB*24*(LL/2)];     // [b][ch][key/2] half2 {k[2p][ch], k[2p+1][ch]}
__device__ uint32_t g_vt[(size_t)NTOK*12];  // [tok][12] bf16x2 d-pairs (packed, no constants)

// ---------------------------------------------------------------------------
// helpers
// ---------------------------------------------------------------------------
__device__ __forceinline__ void mma_tf32(float* c, const uint32_t* a, uint32_t b0, uint32_t b1){
    asm volatile("mma.sync.aligned.m16n8k8.row.col.f32.tf32.tf32.f32 "
        "{%0,%1,%2,%3}, {%4,%5,%6,%7}, {%8,%9}, {%0,%1,%2,%3};"
        : "+f"(c[0]), "+f"(c[1]), "+f"(c[2]), "+f"(c[3])
        : "r"(a[0]), "r"(a[1]), "r"(a[2]), "r"(a[3]), "r"(b0), "r"(b1));
}
__device__ __forceinline__ void mma_f16(float* c, const uint32_t* a, uint32_t b0, uint32_t b1){
    asm volatile("mma.sync.aligned.m16n8k16.row.col.f32.f16.f16.f32 "
        "{%0,%1,%2,%3}, {%4,%5,%6,%7}, {%8,%9}, {%0,%1,%2,%3};"
        : "+f"(c[0]), "+f"(c[1]), "+f"(c[2]), "+f"(c[3])
        : "r"(a[0]), "r"(a[1]), "r"(a[2]), "r"(a[3]), "r"(b0), "r"(b1));
}
__device__ __forceinline__ void mma_bf16(float* c, const uint32_t* a, uint32_t b0, uint32_t b1){
    asm volatile("mma.sync.aligned.m16n8k16.row.col.f32.bf16.bf16.f32 "
        "{%0,%1,%2,%3}, {%4,%5,%6,%7}, {%8,%9}, {%0,%1,%2,%3};"
        : "+f"(c[0]), "+f"(c[1]), "+f"(c[2]), "+f"(c[3])
        : "r"(a[0]), "r"(a[1]), "r"(a[2]), "r"(a[3]), "r"(b0), "r"(b1));
}
__device__ __forceinline__ void ldmx4t(uint32_t& a, uint32_t& b, uint32_t& c, uint32_t& d, uint32_t addr){
    asm volatile("ldmatrix.sync.aligned.m8n8.x4.trans.shared.b16 {%0,%1,%2,%3}, [%4];"
        : "=r"(a), "=r"(b), "=r"(c), "=r"(d) : "r"(addr));
}
__device__ __forceinline__ uint32_t packbf(float hi, float lo){
    uint32_t r;
    asm("cvt.rn.bf16x2.f32 %0, %1, %2;" : "=r"(r) : "f"(hi), "f"(lo));
    return r;
}
__device__ __forceinline__ uint32_t packh2(float hi, float lo){
    uint32_t r;
    asm("cvt.rn.f16x2.f32 %0, %1, %2;" : "=r"(r) : "f"(hi), "f"(lo));
    return r;
}
__device__ __forceinline__ float ex2f(float x){
    float y;
    asm("ex2.approx.f32 %0, %1;" : "=f"(y) : "f"(x));
    return y;
}
__device__ __forceinline__ uint32_t smem_u32(const void* p){
    uint32_t a;
    asm("{ .reg .u64 t; cvta.to.shared.u64 t, %1; cvt.u32.u64 %0, t; }":"=r"(a):"l"(p));
    return a;
}
__device__ __forceinline__ void cp16(uint32_t dst, const void* src){
    asm volatile("cp.async.ca.shared.global [%0], [%1], 16;"::"r"(dst),"l"(src):"memory");
}
#define CP_COMMIT() asm volatile("cp.async.commit_group;":::"memory")
#define CP_WAIT0()  asm volatile("cp.async.wait_group 0;":::"memory")

// ---------------------------------------------------------------------------
// Kernel 1: tf32 MMA QKV projection (unchanged from R16).
// ---------------------------------------------------------------------------
__global__ __launch_bounds__(128) void proj_mma_kernel(
    const float* __restrict__ x, const float* __restrict__ wq,
    const float* __restrict__ wk, const float* __restrict__ wv)
{
    extern __shared__ float sm[];
    float* Xs  = sm;
    float* Wts = sm + POFF_W;

    const int tid  = threadIdx.x;
    const int w    = tid >> 5;
    const int lane = tid & 31;
    const int g    = lane >> 2;
    const int tig  = lane & 3;
    const int tok0 = blockIdx.x * 128;

    float c[2][9][4];
    #pragma unroll
    for (int mt = 0; mt < 2; mt++)
        #pragma unroll
        for (int nt = 0; nt < 9; nt++)
            #pragma unroll
            for (int j = 0; j < 4; j++) c[mt][nt][j] = 0.f;

    #pragma unroll 1
    for (int ch = 0; ch < 4; ch++) {
        __syncthreads();
        {
            const float4* xsrc = reinterpret_cast<const float4*>(x + (size_t)(tok0 + tid)*CH + ch*48);
            float4* xdst = reinterpret_cast<float4*>(Xs + tid*XP);
            #pragma unroll
            for (int i = 0; i < 12; i++) xdst[i] = xsrc[i];
        }
        for (int i = tid; i < 288; i += 128) {
            int cl = i / 6, f4 = i - cl*6;
            int cg = ch*48 + cl;
            float4 aq = *reinterpret_cast<const float4*>(wq + cg*DD + f4*4);
            float4 ak = *reinterpret_cast<const float4*>(wk + cg*DD + f4*4);
            float4 av = *reinterpret_cast<const float4*>(wv + cg*DD + f4*4);
            float* col = Wts + cl;
            col[(f4*4+0)*XP] = aq.x*LOG2E;
            col[(f4*4+1)*XP] = aq.y*LOG2E;
            col[(f4*4+2)*XP] = aq.z*LOG2E;
            col[(f4*4+3)*XP] = aq.w*LOG2E;
            col[(24+f4*4+0)*XP] = ak.x;
            col[(24+f4*4+1)*XP] = ak.y;
            col[(24+f4*4+2)*XP] = ak.z;
            col[(24+f4*4+3)*XP] = ak.w;
            col[(48+f4*4+0)*XP] = av.x;
            col[(48+f4*4+1)*XP] = av.y;
            col[(48+f4*4+2)*XP] = av.z;
            col[(48+f4*4+3)*XP] = av.w;
        }
        __syncthreads();

        #pragma unroll
        for (int ks = 0; ks < 6; ks++) {
            uint32_t a[2][4];
            #pragma unroll
            for (int mt = 0; mt < 2; mt++) {
                const float* r0 = Xs + (w*32 + mt*16 + g)*XP + ks*8 + tig;
                const float* r1 = r0 + 8*XP;
                a[mt][0] = __float_as_uint(r0[0]);
                a[mt][1] = __float_as_uint(r1[0]);
                a[mt][2] = __float_as_uint(r0[4]);
                a[mt][3] = __float_as_uint(r1[4]);
            }
            #pragma unroll
            for (int nt = 0; nt < 9; nt++) {
                const float* br = Wts + (nt*8 + g)*XP + ks*8 + tig;
                uint32_t b0 = __float_as_uint(br[0]);
                uint32_t b1 = __float_as_uint(br[4]);
                mma_tf32(c[0][nt], a[0], b0, b1);
                mma_tf32(c[1][nt], a[1], b0, b1);
            }
        }
    }

    __syncthreads();
    #pragma unroll
    for (int mt = 0; mt < 2; mt++)
        #pragma unroll
        for (int h = 0; h < 2; h++) {
            int row = w*32 + mt*16 + g + h*8;
            #pragma unroll
            for (int nt = 0; nt < 9; nt++) {
                sm[row*76 + nt*8 + 2*tig]     = c[mt][nt][h*2];
                sm[row*76 + nt*8 + 2*tig + 1] = c[mt][nt][h*2+1];
            }
        }
    __syncthreads();

    {
        int tok = tok0 + tid;
        const float* r = sm + tid*76;
        uint32_t qw[12];
        #pragma unroll
        for (int cp = 0; cp < 12; cp++) qw[cp] = packh2(r[2*cp+1], r[2*cp]);
        uint4* qo = reinterpret_cast<uint4*>(g_qh + (size_t)tok*12);
        qo[0] = make_uint4(qw[0], qw[1], qw[2],  qw[3]);
        qo[1] = make_uint4(qw[4], qw[5], qw[6],  qw[7]);
        qo[2] = make_uint4(qw[8], qw[9], qw[10], qw[11]);
    }
    {
        int b0i  = tok0 / LL;
        int koff = (tok0 - b0i*LL) / 2;
        uint32_t* dst = g_kt + (size_t)b0i*24*(LL/2) + koff;
        #pragma unroll
        for (int i = 0; i < 12; i++) {
            int idx = tid + i*128;
            int ch = idx >> 6, p = idx & 63;
            dst[(size_t)ch*(LL/2) + p] =
                packh2(sm[(2*p+1)*76 + 24 + ch], sm[(2*p)*76 + 24 + ch]);
        }
    }
    {
        int tok = tok0 + tid;
        const float* r = sm + tid*76 + 48;
        uint32_t vw[12];
        #pragma unroll
        for (int j = 0; j < 12; j++) vw[j] = packbf(r[2*j+1], r[2*j]);
        uint4* vo = reinterpret_cast<uint4*>(g_vt + (size_t)tok*12);
        vo[0] = make_uint4(vw[0], vw[1], vw[2],  vw[3]);
        vo[1] = make_uint4(vw[4], vw[5], vw[6],  vw[7]);
        vo[2] = make_uint4(vw[8], vw[9], vw[10], vw[11]);
    }
}

// ---------------------------------------------------------------------------
// Kernel 2: mma.sync flash attention. 4 warps = (qhalf, khalf): each warp
// 64 queries x 128 keys per tile (M=64, 32-key chunks). ldmatrix reads halved.
// Max-free softmax; partial (o,l) per khalf merged in epilogue.
// ---------------------------------------------------------------------------
__global__ __launch_bounds__(128, 2) void attn_mma_kernel(
    const float* __restrict__ tensor, const float* __restrict__ wo,
    const float* __restrict__ gammap, float* __restrict__ out)
{
    extern __shared__ float smf[];
    uint32_t* Qh = reinterpret_cast<uint32_t*>(smf) + OFF_Q;
    uint32_t* Kw = reinterpret_cast<uint32_t*>(smf) + OFF_K;
    uint32_t* Vw = reinterpret_cast<uint32_t*>(smf) + OFF_V;
    const uint32_t smb = smem_u32(smf);

    const int tid  = threadIdx.x;
    const int w    = tid >> 5;
    const int lane = tid & 31;
    const int g    = lane >> 2;
    const int tig  = lane & 3;
    const int qhalf = w >> 1;            // query half (0: rows 0-63, 1: rows 64-127)
    const int khalf = w & 1;             // key half of each tile
    const int qt = blockIdx.x, b = blockIdx.y;

    // per-lane ldmatrix row-offset bases (halves)
    const int t8  = lane >> 3;
    const int tg8 = lane & 7;
    const uint32_t kaddr0 = smb + OFF_K*4 + (((t8 & 1)*8 + tg8)*(KROWW*2) + (t8 >> 1)*8)*2;
    const uint32_t vaddr0 = smb + OFF_V*4 + (((t8 & 1)*8 + tg8)*(VROWW*2) + (t8 >> 1)*8)*2;

    // ---- stage Q tile: 12 packed words + 4 zero words per row ----
    {
        int tok = b*LL + qt*BQ + tid;
        const uint4* src = reinterpret_cast<const uint4*>(g_qh + (size_t)tok*12);
        uint4* dst = reinterpret_cast<uint4*>(Qh + tid*QPH);
        dst[0] = src[0]; dst[1] = src[1]; dst[2] = src[2];
        dst[3] = make_uint4(0u, 0u, 0u, 0u);
    }
    // ---- static pads (once): K ch-rows 24..31 zero; V words 12..15 per key ----
    for (int i = tid; i < 8*KROWW; i += 128) Kw[24*KROWW + i] = 0;
    #pragma unroll
    for (int r = 0; r < 2; r++) {
        int key = tid + r*128;
        Vw[key*VROWW + 12] = 0x00003F80u;   // d24 = bf16 1.0 (l column)
        Vw[key*VROWW + 13] = 0u;
        Vw[key*VROWW + 14] = 0u;
        Vw[key*VROWW + 15] = 0u;
    }
    __syncthreads();

    // ---- Q fragments: warp owns 64 rows (4 m-tiles), 2 k-steps of 16 ----
    uint32_t qa[4][2][4];
    #pragma unroll
    for (int mt = 0; mt < 4; mt++)
        #pragma unroll
        for (int ks = 0; ks < 2; ks++) {
            const uint32_t* r0 = Qh + (qhalf*64 + mt*16 + g)*QPH + ks*8 + tig;
            const uint32_t* r1 = r0 + 8*QPH;
            qa[mt][ks][0] = r0[0];
            qa[mt][ks][1] = r1[0];
            qa[mt][ks][2] = r0[4];
            qa[mt][ks][3] = r1[4];
        }

    // O accumulators: 4 m-tiles x 4 n-tiles (3 V dims + ones-column = l)
    float o[4][4][4];
    #pragma unroll
    for (int mt = 0; mt < 4; mt++)
        #pragma unroll
        for (int dn = 0; dn < 4; dn++)
            #pragma unroll
            for (int j = 0; j < 4; j++) o[mt][dn][j] = 0.f;

    // ================= main loop =================
    #pragma unroll 1
    for (int kt = 0; kt < NKT; kt++) {
        __syncthreads();
        {
            // K: 24 ch-rows x 32 word-groups = 768 cp16
            const uint32_t* ksrc = g_kt + (size_t)b*24*(LL/2) + kt*(BK/2);
            #pragma unroll
            for (int i = 0; i < 6; i++) {
                int idx = tid + i*128;           // < 768
                int ch = idx >> 5, grp = idx & 31;
                cp16(smb + (OFF_K + ch*KROWW + grp*4)*4, ksrc + (size_t)ch*(LL/2) + grp*4);
            }
            // V: flat contiguous 768 cp16 (256 keys x 3 groups)
            const uint32_t* vsrc = g_vt + ((size_t)b*LL + kt*BK)*12;
            #pragma unroll
            for (int i = 0; i < 6; i++) {
                int idx = tid + i*128;           // < 768
                int key = idx / 3;               // dst word = idx*4 + key*8
                cp16(smb + (OFF_V + idx*4 + key*8)*4, vsrc + (size_t)idx*4);
            }
            CP_COMMIT();
            CP_WAIT0();
        }
        __syncthreads();

        // ---- 4 chunks of 32 keys within this warp's key half ----
        #pragma unroll 1
        for (int cki = 0; cki < 4; cki++) {
            const int ckey = khalf*128 + cki*32;   // key offset within tile
            float s[4][4][4];
            #pragma unroll
            for (int mt = 0; mt < 4; mt++)
                #pragma unroll
                for (int nt = 0; nt < 4; nt++)
                    #pragma unroll
                    for (int j = 0; j < 4; j++) s[mt][nt][j] = 0.f;

            // S = Q K^T (fp16), log2 units; K frags via ldmatrix (shared by 4 m-tiles)
            #pragma unroll
            for (int ks = 0; ks < 2; ks++)
                #pragma unroll
                for (int ntp = 0; ntp < 2; ntp++) {
                    uint32_t b0, b1, b2, b3;
                    ldmx4t(b0, b1, b2, b3,
                           kaddr0 + (uint32_t)(ks*16*(KROWW*2) + ckey + ntp*16)*2);
                    #pragma unroll
                    for (int mt = 0; mt < 4; mt++) {
                        mma_f16(s[mt][2*ntp],   qa[mt][ks], b0, b1);
                        mma_f16(s[mt][2*ntp+1], qa[mt][ks], b2, b3);
                    }
                }

            // p = 2^s
            #pragma unroll
            for (int mt = 0; mt < 4; mt++)
                #pragma unroll
                for (int nt = 0; nt < 4; nt++)
                    #pragma unroll
                    for (int j = 0; j < 4; j++)
                        s[mt][nt][j] = ex2f(s[mt][nt][j]);

            // O += P V (bf16); V frags shared by 4 m-tiles; n-tile 3 carries l
            #pragma unroll
            for (int ks2 = 0; ks2 < 2; ks2++) {
                uint32_t pa[4][4];
                #pragma unroll
                for (int mt = 0; mt < 4; mt++) {
                    pa[mt][0] = packbf(s[mt][ks2*2][1],   s[mt][ks2*2][0]);
                    pa[mt][1] = packbf(s[mt][ks2*2][3],   s[mt][ks2*2][2]);
                    pa[mt][2] = packbf(s[mt][ks2*2+1][1], s[mt][ks2*2+1][0]);
                    pa[mt][3] = packbf(s[mt][ks2*2+1][3], s[mt][ks2*2+1][2]);
                }
                #pragma unroll
                for (int dnp = 0; dnp < 2; dnp++) {
                    uint32_t b0, b1, b2, b3;
                    ldmx4t(b0, b1, b2, b3,
                           vaddr0 + (uint32_t)((ckey + ks2*16)*(VROWW*2) + dnp*16)*2);
                    #pragma unroll
                    for (int mt = 0; mt < 4; mt++) {
                        mma_bf16(o[mt][2*dnp],   pa[mt], b0, b1);
                        mma_bf16(o[mt][2*dnp+1], pa[mt], b2, b3);
                    }
                }
            }
        }
    }

    // ---- write UNnormalized partial (o, l) to bounce region[khalf] ----
    __syncthreads();
    {
        float* bnc = smf + khalf*BNC1;
        #pragma unroll
        for (int mt = 0; mt < 4; mt++)
            #pragma unroll
            for (int h = 0; h < 2; h++) {
                int row = qhalf*64 + mt*16 + g + h*8;
                #pragma unroll
                for (int dn = 0; dn < 3; dn++) {
                    bnc[row*APAD + dn*8 + 2*tig]     = o[mt][dn][h*2];
                    bnc[row*APAD + dn*8 + 2*tig + 1] = o[mt][dn][h*2+1];
                }
                if (tig == 0) bnc[row*APAD + 24] = o[mt][3][h*2];   // partial l
            }
        float4* wd = reinterpret_cast<float4*>(smf + WOFF);
        const float4* ws = reinterpret_cast<const float4*>(wo);
        #pragma unroll
        for (int i = 0; i < 9; i++) wd[tid + i*128] = ws[tid + i*128];
    }
    __syncthreads();

    // ---- epilogue: merge halves, normalize, out = tensor + gamma*attn@Wo ----
    float attn[DD];
    {
        float l = smf[tid*APAD + 24] + smf[BNC1 + tid*APAD + 24];
        float inv = 1.0f / l;
        #pragma unroll
        for (int d = 0; d < DD; d++)
            attn[d] = (smf[tid*APAD + d] + smf[BNC1 + tid*APAD + d]) * inv;
    }

    float gm = *gammap;
    int tok = b*LL + qt*BQ + tid;
    const float4* tr = reinterpret_cast<const float4*>(tensor + (size_t)tok * CH);
    float4* orow = reinterpret_cast<float4*>(out + (size_t)tok * CH);
    const float4* wos = reinterpret_cast<const float4*>(smf + WOFF);

    #pragma unroll 1
    for (int c4 = 0; c4 < CH/4; c4++) {
        float4 t = tr[c4];
        float sx = 0.f, sy = 0.f, sz = 0.f, sw = 0.f;
        #pragma unroll
        for (int d = 0; d < DD; d++) {
            float4 wv4 = wos[d*48 + c4];
            sx = fmaf(attn[d], wv4.x, sx);
            sy = fmaf(attn[d], wv4.y, sy);
            sz = fmaf(attn[d], wv4.z, sz);
            sw = fmaf(attn[d], wv4.w, sw);
        }
        t.x = fmaf(gm, sx, t.x);
        t.y = fmaf(gm, sy, t.y);
        t.z = fmaf(gm, sz, t.z);
        t.w = fmaf(gm, sw, t.w);
        orow[c4] = t;
    }
}

extern "C" void kernel_launch(void* const* d_in, const int* in_sizes, int n_in,
                              void* d_out, int out_size)
{
    const float* tensor = (const float*)d_in[0];
    const float* wq     = (const float*)d_in[1];
    const float* wk     = (const float*)d_in[2];
    const float* wv     = (const float*)d_in[3];
    const float* wo     = (const float*)d_in[4];
    const float* gamma  = (const float*)d_in[5];
    float* out = (float*)d_out;

    cudaFuncSetAttribute(attn_mma_kernel, cudaFuncAttributeMaxDynamicSharedMemorySize, SM_U32*4);

    proj_mma_kernel<<<NTOK/128, 128, P_FLOATS*4>>>(tensor, wq, wk, wv);

    dim3 g2(LL/BQ, BB);
    attn_mma_kernel<<<g2, 128, SM_U32*4>>>(tensor, wo, gamma, out);
}